// round 3
// baseline (speedup 1.0000x reference)
#include <cuda_runtime.h>
#include <math.h>

// Problem constants
#define BB 4
#define TT 2048
#define CC 1024
#define HH 16
#define DD 64
#define MTOT (BB * TT)          // 8192
#define FULLM 0xffffffffu
#define SC_LOG2E 0.18033688f    // (1/sqrt(64)) * log2(e)

// Scratch (allocation is banned -> __device__ globals)
__device__ float g_Q[BB * HH * TT * DD];
__device__ float g_K[BB * HH * TT * DD];
__device__ float g_V[BB * HH * TT * DD];
__device__ float g_Y[BB * TT * CC];

// ---------------------------------------------------------------------------
// TF32 + MMA + LDSM helpers
// ---------------------------------------------------------------------------
__device__ __forceinline__ unsigned f2tf(float x) {
    unsigned u;
    asm("cvt.rna.tf32.f32 %0, %1;" : "=r"(u) : "f"(x));
    return u;
}
__device__ __forceinline__ float tf32f(float x) { return __uint_as_float(f2tf(x)); }
__device__ __forceinline__ float4 cvt4(float4 v) {
    return make_float4(tf32f(v.x), tf32f(v.y), tf32f(v.z), tf32f(v.w));
}

// D = A(m16k8,row) * B(k8n8,col) + D, tf32 inputs, f32 accum
__device__ __forceinline__ void mma8(float* c, const unsigned* a, const unsigned* b) {
    asm volatile(
        "mma.sync.aligned.m16n8k8.row.col.f32.tf32.tf32.f32 "
        "{%0,%1,%2,%3}, {%4,%5,%6,%7}, {%8,%9}, {%0,%1,%2,%3};\n"
        : "+f"(c[0]), "+f"(c[1]), "+f"(c[2]), "+f"(c[3])
        : "r"(a[0]), "r"(a[1]), "r"(a[2]), "r"(a[3]), "r"(b[0]), "r"(b[1]));
}

__device__ __forceinline__ void ldsm4(unsigned& r0, unsigned& r1, unsigned& r2,
                                      unsigned& r3, unsigned addr) {
    asm volatile("ldmatrix.sync.aligned.m8n8.x4.shared.b16 {%0,%1,%2,%3}, [%4];"
                 : "=r"(r0), "=r"(r1), "=r"(r2), "=r"(r3) : "r"(addr));
}

// Swizzled smem layouts (rows paired into lines; 16-byte chunks).
// 16-float rows (GEMM tiles): c in 0..3
__device__ __forceinline__ int idx16(int row, int c) {
    return ((row >> 1) << 5) + (((c + ((row & 1) << 2)) ^ ((row >> 1) & 7)) << 2);
}
// 64-float rows (attention tiles): c in 0..15
__device__ __forceinline__ int idx64(int row, int c) {
    return ((row >> 1) << 7) + (((c + ((row & 1) << 4)) ^ ((row >> 1) & 7)) << 2);
}

// ---------------------------------------------------------------------------
// TF32 tensor-core GEMM, ldmatrix-fed, double-buffered.
// 128x128 block, BK=16, 256 threads (8 warps 4x2; warp tile 32x64).
// MODE 0: scatter into g_Q/g_K/g_V ([B,H,T,D]); MODE 1: plain store.
// ---------------------------------------------------------------------------
template <int MODE>
__global__ __launch_bounds__(256) void gemm_tf32(
    const float* __restrict__ A, const float* __restrict__ Bm,
    float* __restrict__ C, int M, int N, int K)
{
    __shared__ float As[2][2048];
    __shared__ float Bs[2][2048];

    const int tid = threadIdx.x;
    const int bm = blockIdx.y * 128;
    const int bn = blockIdx.x * 128;
    const int lane = tid & 31, wid = tid >> 5;
    const int wm = (wid & 3) * 32;
    const int wn = (wid >> 2) * 64;
    const int g = lane >> 2, r = lane & 3;
    const int rl = (lane & 7) + ((lane >> 3) & 1) * 8;  // ldsm row offset
    const int chi = lane >> 4;                          // ldsm chunk offset

    // Loaders
    const int ar = tid >> 1;            // A row
    const int ac = (tid & 1) * 2;       // A chunk base (2 chunks of 4 k)
    const int bnl = tid & 127;          // B col (n)
    const int bc = (tid >> 7) * 2;      // B chunk base

    const float* Ap = A + (size_t)(bm + ar) * K + ac * 4;
    const float* Bp = Bm + (size_t)(bc * 4) * N + bn + bnl;

    float4 a0 = *(const float4*)Ap;
    float4 a1 = *(const float4*)(Ap + 4);
    float bv[8];
#pragma unroll
    for (int i = 0; i < 8; i++) bv[i] = Bp[(size_t)i * N];

    // Stage 0
    *(float4*)&As[0][idx16(ar, ac)] = cvt4(a0);
    *(float4*)&As[0][idx16(ar, ac + 1)] = cvt4(a1);
    *(float4*)&Bs[0][idx16(bnl, bc)] =
        make_float4(tf32f(bv[0]), tf32f(bv[1]), tf32f(bv[2]), tf32f(bv[3]));
    *(float4*)&Bs[0][idx16(bnl, bc + 1)] =
        make_float4(tf32f(bv[4]), tf32f(bv[5]), tf32f(bv[6]), tf32f(bv[7]));
    __syncthreads();

    float acc[2][8][4];
#pragma unroll
    for (int mi = 0; mi < 2; mi++)
#pragma unroll
        for (int nj = 0; nj < 8; nj++)
#pragma unroll
            for (int c = 0; c < 4; c++) acc[mi][nj][c] = 0.0f;

    const unsigned asb = (unsigned)__cvta_generic_to_shared(&As[0][0]);
    const unsigned bsb = (unsigned)__cvta_generic_to_shared(&Bs[0][0]);

    const int NTT = K / 16;
    for (int it = 0; it < NTT; it++) {
        const int cur = it & 1;
        const bool hasNext = (it + 1 < NTT);
        if (hasNext) {
            const float* Ap2 = Ap + (it + 1) * 16;
            a0 = *(const float4*)Ap2;
            a1 = *(const float4*)(Ap2 + 4);
            const float* Bp2 = Bp + (size_t)(it + 1) * 16 * N;
#pragma unroll
            for (int i = 0; i < 8; i++) bv[i] = Bp2[(size_t)i * N];
        }

        const unsigned ab = asb + cur * 8192;
        const unsigned bb = bsb + cur * 8192;
#pragma unroll
        for (int ks = 0; ks < 2; ks++) {
            const int c = 2 * ks + chi;
            unsigned af[2][4];
#pragma unroll
            for (int mi = 0; mi < 2; mi++) {
                const int row = wm + 16 * mi + rl;
                ldsm4(af[mi][0], af[mi][1], af[mi][2], af[mi][3],
                      ab + 4 * idx16(row, c));
            }
#pragma unroll
            for (int njp = 0; njp < 4; njp++) {
                const int row = wn + 16 * njp + rl;
                unsigned b0, b1, b2, b3;
                ldsm4(b0, b1, b2, b3, bb + 4 * idx16(row, c));
                unsigned bfa[2] = {b0, b2};
                unsigned bfb[2] = {b1, b3};
                mma8(acc[0][2 * njp], af[0], bfa);
                mma8(acc[1][2 * njp], af[1], bfa);
                mma8(acc[0][2 * njp + 1], af[0], bfb);
                mma8(acc[1][2 * njp + 1], af[1], bfb);
            }
        }

        if (hasNext) {
            const int nxt = cur ^ 1;
            *(float4*)&As[nxt][idx16(ar, ac)] = cvt4(a0);
            *(float4*)&As[nxt][idx16(ar, ac + 1)] = cvt4(a1);
            *(float4*)&Bs[nxt][idx16(bnl, bc)] =
                make_float4(tf32f(bv[0]), tf32f(bv[1]), tf32f(bv[2]), tf32f(bv[3]));
            *(float4*)&Bs[nxt][idx16(bnl, bc + 1)] =
                make_float4(tf32f(bv[4]), tf32f(bv[5]), tf32f(bv[6]), tf32f(bv[7]));
        }
        __syncthreads();
    }

    // Epilogue
#pragma unroll
    for (int mi = 0; mi < 2; mi++) {
        const int mA = bm + wm + 16 * mi + g;  // rows mA (c0,c1), mA+8 (c2,c3)
        if (MODE == 0) {
            const int bb2 = mA >> 11;
            const int ttA = mA & 2047;
#pragma unroll
            for (int nj = 0; nj < 8; nj++) {
                const int n = bn + wn + 8 * nj + 2 * r;
                const int sel = n >> 10;
                const int c = n & 1023;
                const int hh = c >> 6;
                const int dd = c & 63;
                float* dst = (sel == 0) ? g_Q : (sel == 1 ? g_K : g_V);
                float* base = dst + (((size_t)bb2 * HH + hh) * TT) * DD + dd;
                *(float2*)(base + (size_t)ttA * DD) =
                    make_float2(acc[mi][nj][0], acc[mi][nj][1]);
                *(float2*)(base + (size_t)(ttA + 8) * DD) =
                    make_float2(acc[mi][nj][2], acc[mi][nj][3]);
            }
        } else {
#pragma unroll
            for (int nj = 0; nj < 8; nj++) {
                const int n = bn + wn + 8 * nj + 2 * r;
                *(float2*)&C[(size_t)mA * N + n] =
                    make_float2(acc[mi][nj][0], acc[mi][nj][1]);
                *(float2*)&C[(size_t)(mA + 8) * N + n] =
                    make_float2(acc[mi][nj][2], acc[mi][nj][3]);
            }
        }
    }
}

// ---------------------------------------------------------------------------
// Flash attention, tf32 MMA, ldmatrix-fed.
// Block = 128 q-rows of one (b,h), 8 warps. KV tiles of 64.
// Warp owns 16 q rows. Online softmax in log2 domain.
// ---------------------------------------------------------------------------
__global__ __launch_bounds__(256) void attn_mma_kernel()
{
    const int bh = blockIdx.y;
    const int b = bh >> 4, h = bh & 15;
    const int qi = gridDim.x - 1 - blockIdx.x;  // heavy blocks first
    const int q0 = qi * 128;
    const int tid = threadIdx.x;
    const int w = tid >> 5, lane = tid & 31;
    const int g = lane >> 2, r = lane & 3;
    const int rl = (lane & 7) + ((lane >> 3) & 1) * 8;
    const int chi = lane >> 4;

    __shared__ float Ks[4096];  // [kv=64][d=64], swizzled (idx64)
    __shared__ float Vs[4096];  // [d=64][kv=64], swizzled (idx64)

    const unsigned ksb = (unsigned)__cvta_generic_to_shared(&Ks[0]);
    const unsigned vsb = (unsigned)__cvta_generic_to_shared(&Vs[0]);

    const size_t hoff = ((size_t)b * HH + h) * TT * DD;
    const float* Qg = g_Q + hoff;
    const float* Kg = g_K + hoff;
    const float* Vg = g_V + hoff;

    // Q fragments straight from gmem (read once)
    const int mrow = q0 + 16 * w + g;
    unsigned qf[8][4];
#pragma unroll
    for (int ks = 0; ks < 8; ks++) {
        qf[ks][0] = f2tf(Qg[(size_t)mrow * DD + 8 * ks + r]);
        qf[ks][1] = f2tf(Qg[(size_t)(mrow + 8) * DD + 8 * ks + r]);
        qf[ks][2] = f2tf(Qg[(size_t)mrow * DD + 8 * ks + 4 + r]);
        qf[ks][3] = f2tf(Qg[(size_t)(mrow + 8) * DD + 8 * ks + 4 + r]);
    }

    float oacc[8][4];
#pragma unroll
    for (int dt = 0; dt < 8; dt++)
#pragma unroll
        for (int c = 0; c < 4; c++) oacc[dt][c] = 0.0f;
    float mA = -1e30f, mB = -1e30f, lA = 0.0f, lB = 0.0f;

    const int qA = mrow;
    const int qB = mrow + 8;

    // Staging assignments
    const int dqK = tid & 15;   // K: d chunk
    const int kvK = tid >> 4;   // K: kv row base (0..15)
    const int dV = tid & 63;    // V: d row
    const int cgV = tid >> 6;   // V: chunk group (0..3)

    for (int kv0 = 0; kv0 < q0 + 128; kv0 += 64) {
        __syncthreads();
        // K tile: rows kv, 64 d, coalesced LDG.128 + swizzled STS.128
#pragma unroll
        for (int j = 0; j < 4; j++) {
            const int row = kvK + 16 * j;
            float4 kx = *(const float4*)&Kg[(size_t)(kv0 + row) * DD + 4 * dqK];
            *(float4*)&Ks[idx64(row, dqK)] = cvt4(kx);
        }
        // V tile transposed: rows d, chunks of 4 kv
#pragma unroll
        for (int i = 0; i < 4; i++) {
            const int c = 4 * cgV + i;
            const int kvb = kv0 + 4 * c;
            float4 vv;
            vv.x = Vg[(size_t)(kvb + 0) * DD + dV];
            vv.y = Vg[(size_t)(kvb + 1) * DD + dV];
            vv.z = Vg[(size_t)(kvb + 2) * DD + dV];
            vv.w = Vg[(size_t)(kvb + 3) * DD + dV];
            *(float4*)&Vs[idx64(dV, c)] = cvt4(vv);
        }
        __syncthreads();

        // S = Q K^T  (warp: 16 x 64)
        float sacc[8][4];
#pragma unroll
        for (int j = 0; j < 8; j++)
#pragma unroll
            for (int c = 0; c < 4; c++) sacc[j][c] = 0.0f;
#pragma unroll
        for (int ks = 0; ks < 8; ks++) {
            const int c = 2 * ks + chi;
#pragma unroll
            for (int njp = 0; njp < 4; njp++) {
                const int row = 16 * njp + rl;
                unsigned b0, b1, b2, b3;
                ldsm4(b0, b1, b2, b3, ksb + 4 * idx64(row, c));
                unsigned bfa[2] = {b0, b2};
                unsigned bfb[2] = {b1, b3};
                mma8(sacc[2 * njp], qf[ks], bfa);
                mma8(sacc[2 * njp + 1], qf[ks], bfb);
            }
        }

        // scale to log2 domain + causal mask, track tile row max
        const bool diag = (kv0 + 63 > q0 + 16 * w);
        float tmA = -1e30f, tmB = -1e30f;
#pragma unroll
        for (int j = 0; j < 8; j++) {
            const int kc = kv0 + 8 * j + 2 * r;
            float t0 = sacc[j][0] * SC_LOG2E;
            float t1 = sacc[j][1] * SC_LOG2E;
            float t2 = sacc[j][2] * SC_LOG2E;
            float t3 = sacc[j][3] * SC_LOG2E;
            if (diag) {
                if (kc > qA) t0 = -1e30f;
                if (kc + 1 > qA) t1 = -1e30f;
                if (kc > qB) t2 = -1e30f;
                if (kc + 1 > qB) t3 = -1e30f;
            }
            sacc[j][0] = t0; sacc[j][1] = t1; sacc[j][2] = t2; sacc[j][3] = t3;
            tmA = fmaxf(tmA, fmaxf(t0, t1));
            tmB = fmaxf(tmB, fmaxf(t2, t3));
        }
        tmA = fmaxf(tmA, __shfl_xor_sync(FULLM, tmA, 1));
        tmA = fmaxf(tmA, __shfl_xor_sync(FULLM, tmA, 2));
        tmB = fmaxf(tmB, __shfl_xor_sync(FULLM, tmB, 1));
        tmB = fmaxf(tmB, __shfl_xor_sync(FULLM, tmB, 2));

        const float mnA = fmaxf(mA, tmA);
        const float mnB = fmaxf(mB, tmB);
        const float scA = exp2f(mA - mnA);
        const float scB = exp2f(mB - mnB);
        mA = mnA; mB = mnB;

        // exponentiate (tf32-rounded so l matches the PV numerator), row sums
        float smA = 0.0f, smB = 0.0f;
#pragma unroll
        for (int j = 0; j < 8; j++) {
            float p0 = tf32f(exp2f(sacc[j][0] - mA));
            float p1 = tf32f(exp2f(sacc[j][1] - mA));
            float p2 = tf32f(exp2f(sacc[j][2] - mB));
            float p3 = tf32f(exp2f(sacc[j][3] - mB));
            sacc[j][0] = p0; sacc[j][1] = p1; sacc[j][2] = p2; sacc[j][3] = p3;
            smA += p0 + p1;
            smB += p2 + p3;
        }
        smA += __shfl_xor_sync(FULLM, smA, 1);
        smA += __shfl_xor_sync(FULLM, smA, 2);
        smB += __shfl_xor_sync(FULLM, smB, 1);
        smB += __shfl_xor_sync(FULLM, smB, 2);
        lA = lA * scA + smA;
        lB = lB * scB + smB;

        // rescale O
#pragma unroll
        for (int dt = 0; dt < 8; dt++) {
            oacc[dt][0] *= scA; oacc[dt][1] *= scA;
            oacc[dt][2] *= scB; oacc[dt][3] *= scB;
        }

        // O += P @ V  (P: C-frag -> A-frag via shfl; V B-frags via ldsm)
        const int s0 = (lane & ~3) | (r >> 1);
        const int s1 = s0 + 2;
        const bool odd = (r & 1);
#pragma unroll
        for (int ks = 0; ks < 8; ks++) {
            float p00 = __shfl_sync(FULLM, sacc[ks][0], s0);
            float p01 = __shfl_sync(FULLM, sacc[ks][1], s0);
            float p02 = __shfl_sync(FULLM, sacc[ks][2], s0);
            float p03 = __shfl_sync(FULLM, sacc[ks][3], s0);
            float p10 = __shfl_sync(FULLM, sacc[ks][0], s1);
            float p11 = __shfl_sync(FULLM, sacc[ks][1], s1);
            float p12 = __shfl_sync(FULLM, sacc[ks][2], s1);
            float p13 = __shfl_sync(FULLM, sacc[ks][3], s1);
            unsigned pf[4];
            pf[0] = __float_as_uint(odd ? p01 : p00);
            pf[1] = __float_as_uint(odd ? p03 : p02);
            pf[2] = __float_as_uint(odd ? p11 : p10);
            pf[3] = __float_as_uint(odd ? p13 : p12);
            const int c = 2 * ks + chi;
#pragma unroll
            for (int dtp = 0; dtp < 4; dtp++) {
                const int row = 16 * dtp + rl;
                unsigned b0, b1, b2, b3;
                ldsm4(b0, b1, b2, b3, vsb + 4 * idx64(row, c));
                unsigned bfa[2] = {b0, b2};
                unsigned bfb[2] = {b1, b3};
                mma8(oacc[2 * dtp], pf, bfa);
                mma8(oacc[2 * dtp + 1], pf, bfb);
            }
        }
    }

    // Epilogue: y[b, t, h*64 + d]
    const float ivA = 1.0f / lA;
    const float ivB = 1.0f / lB;
    float* yA = g_Y + ((size_t)b * TT + qA) * CC + h * DD;
    float* yB = g_Y + ((size_t)b * TT + qB) * CC + h * DD;
#pragma unroll
    for (int dt = 0; dt < 8; dt++) {
        const int d = 8 * dt + 2 * r;
        *(float2*)(yA + d) = make_float2(oacc[dt][0] * ivA, oacc[dt][1] * ivA);
        *(float2*)(yB + d) = make_float2(oacc[dt][2] * ivB, oacc[dt][3] * ivB);
    }
}

// ---------------------------------------------------------------------------
extern "C" void kernel_launch(void* const* d_in, const int* in_sizes, int n_in,
                              void* d_out, int out_size)
{
    const float* x = (const float*)d_in[0];       // [B,T,C]
    const float* W_attn = (const float*)d_in[1];  // [C,3C]
    const float* W_proj = (const float*)d_in[2];  // [C,C]
    float* out = (float*)d_out;                   // [B,T,C]

    (void)in_sizes; (void)n_in; (void)out_size;

    void* yptr = nullptr;
    cudaGetSymbolAddress(&yptr, g_Y);  // pure query, capture-safe

    // 1) QKV projection (tf32 MMA) with scatter into Q/K/V
    {
        dim3 grid(3 * CC / 128, MTOT / 128);  // (24, 64)
        gemm_tf32<0><<<grid, 256>>>(x, W_attn, nullptr, MTOT, 3 * CC, CC);
    }
    // 2) Causal flash attention (tf32 MMA) -> g_Y [B,T,C]
    {
        dim3 grid(TT / 128, BB * HH);  // (16, 64)
        attn_mma_kernel<<<grid, 256>>>();
    }
    // 3) Output projection (tf32 MMA)
    {
        dim3 grid(CC / 128, MTOT / 128);  // (8, 64)
        gemm_tf32<1><<<grid, 256>>>((const float*)yptr, W_proj, out,
                                    MTOT, CC, CC);
    }
}

// round 5
// speedup vs baseline: 1.0687x; 1.0687x over previous
#include <cuda_runtime.h>
#include <math.h>

// Problem constants
#define BB 4
#define TT 2048
#define CC 1024
#define HH 16
#define DD 64
#define MTOT (BB * TT)          // 8192
#define FULLM 0xffffffffu
#define SC_LOG2E 0.18033688f    // (1/sqrt(64)) * log2(e)

// Scratch (allocation is banned -> __device__ globals)
__device__ float g_Q[BB * HH * TT * DD];
__device__ float g_K[BB * HH * TT * DD];
__device__ float g_V[BB * HH * TT * DD];
__device__ float g_Y[BB * TT * CC];
__device__ float g_X[MTOT * CC];        // tf32-rounded x
__device__ float g_Wa[CC * 3 * CC];     // tf32-rounded W_attn
__device__ float g_Wp[CC * CC];         // tf32-rounded W_proj

// ---------------------------------------------------------------------------
// TF32 + MMA + LDSM helpers
// ---------------------------------------------------------------------------
__device__ __forceinline__ unsigned f2tf(float x) {
    unsigned u;
    asm("cvt.rna.tf32.f32 %0, %1;" : "=r"(u) : "f"(x));
    return u;
}
__device__ __forceinline__ float tf32f(float x) { return __uint_as_float(f2tf(x)); }
__device__ __forceinline__ float4 cvt4(float4 v) {
    return make_float4(tf32f(v.x), tf32f(v.y), tf32f(v.z), tf32f(v.w));
}

// D = A(m16k8,row) * B(k8n8,col) + D, tf32 inputs, f32 accum
__device__ __forceinline__ void mma8(float* c, const unsigned* a, const unsigned* b) {
    asm volatile(
        "mma.sync.aligned.m16n8k8.row.col.f32.tf32.tf32.f32 "
        "{%0,%1,%2,%3}, {%4,%5,%6,%7}, {%8,%9}, {%0,%1,%2,%3};\n"
        : "+f"(c[0]), "+f"(c[1]), "+f"(c[2]), "+f"(c[3])
        : "r"(a[0]), "r"(a[1]), "r"(a[2]), "r"(a[3]), "r"(b[0]), "r"(b[1]));
}

__device__ __forceinline__ void ldsm4(unsigned& r0, unsigned& r1, unsigned& r2,
                                      unsigned& r3, unsigned addr) {
    asm volatile("ldmatrix.sync.aligned.m8n8.x4.shared.b16 {%0,%1,%2,%3}, [%4];"
                 : "=r"(r0), "=r"(r1), "=r"(r2), "=r"(r3) : "r"(addr));
}

// Swizzled smem layouts (rows paired into 128B lines; 16-byte chunks).
// 16-float rows (GEMM tiles): c in 0..3
__device__ __forceinline__ int idx16(int row, int c) {
    return ((row >> 1) << 5) + (((c + ((row & 1) << 2)) ^ ((row >> 1) & 7)) << 2);
}
// 64-float rows (attention tiles): c in 0..15
__device__ __forceinline__ int idx64(int row, int c) {
    return ((row >> 1) << 7) + (((c + ((row & 1) << 4)) ^ ((row >> 1) & 7)) << 2);
}

// ---------------------------------------------------------------------------
// Pre-pass: round fp32 -> tf32-exact fp32 (elementwise, float4)
// ---------------------------------------------------------------------------
__global__ void round_tf32_kernel(const float* __restrict__ in,
                                  float* __restrict__ out, int n4)
{
    const int i = blockIdx.x * blockDim.x + threadIdx.x;
    if (i < n4) {
        float4 v = ((const float4*)in)[i];
        ((float4*)out)[i] = cvt4(v);
    }
}

// ---------------------------------------------------------------------------
// TF32 tensor-core GEMM, ldmatrix-fed, double-buffered, no in-loop cvt.
// 128x128 block, BK=16, 256 threads (8 warps 4x2; warp tile 32x64).
// Inputs must be tf32-exact fp32 already.
// MODE 0: scatter into g_Q/g_K/g_V ([B,H,T,D], tf32-rounded); MODE 1: plain.
// ---------------------------------------------------------------------------
template <int MODE>
__global__ __launch_bounds__(256, 2) void gemm_tf32(
    const float* __restrict__ A, const float* __restrict__ Bm,
    float* __restrict__ C, int M, int N, int K)
{
    __shared__ float As[2][2048];
    __shared__ float Bs[2][2048];

    const int tid = threadIdx.x;
    const int bm = blockIdx.y * 128;
    const int bn = blockIdx.x * 128;
    const int lane = tid & 31, wid = tid >> 5;
    const int wm = (wid & 3) * 32;
    const int wn = (wid >> 2) * 64;
    const int g = lane >> 2, r = lane & 3;
    const int rl = (lane & 7) + ((lane >> 3) & 1) * 8;  // ldsm row offset
    const int chi = lane >> 4;                          // ldsm chunk offset

    // Loaders
    const int ar = tid >> 1;            // A row
    const int ac = (tid & 1) * 2;       // A chunk base (2 chunks of 4 k)
    const int bnl = tid & 127;          // B col (n)
    const int bc = (tid >> 7) * 2;      // B chunk base

    const float* Ap = A + (size_t)(bm + ar) * K + ac * 4;
    const float* Bp = Bm + (size_t)(bc * 4) * N + bn + bnl;

    // Hoisted ldsm offsets (bytes), k-loop invariant
    unsigned aoff[2][2], boff[2][4];
#pragma unroll
    for (int ks = 0; ks < 2; ks++) {
        const int c = 2 * ks + chi;
#pragma unroll
        for (int mi = 0; mi < 2; mi++)
            aoff[ks][mi] = 4 * idx16(wm + 16 * mi + rl, c);
#pragma unroll
        for (int njp = 0; njp < 4; njp++)
            boff[ks][njp] = 4 * idx16(wn + 16 * njp + rl, c);
    }

    float4 a0 = *(const float4*)Ap;
    float4 a1 = *(const float4*)(Ap + 4);
    float bv[8];
#pragma unroll
    for (int i = 0; i < 8; i++) bv[i] = Bp[(size_t)i * N];

    const int sa0 = idx16(ar, ac), sa1 = idx16(ar, ac + 1);
    const int sb0 = idx16(bnl, bc), sb1 = idx16(bnl, bc + 1);

    // Stage 0
    *(float4*)&As[0][sa0] = a0;
    *(float4*)&As[0][sa1] = a1;
    *(float4*)&Bs[0][sb0] = make_float4(bv[0], bv[1], bv[2], bv[3]);
    *(float4*)&Bs[0][sb1] = make_float4(bv[4], bv[5], bv[6], bv[7]);
    __syncthreads();

    float acc[2][8][4];
#pragma unroll
    for (int mi = 0; mi < 2; mi++)
#pragma unroll
        for (int nj = 0; nj < 8; nj++)
#pragma unroll
            for (int c = 0; c < 4; c++) acc[mi][nj][c] = 0.0f;

    const unsigned asb = (unsigned)__cvta_generic_to_shared(&As[0][0]);
    const unsigned bsb = (unsigned)__cvta_generic_to_shared(&Bs[0][0]);

    const int NTT = K / 16;
    for (int it = 0; it < NTT; it++) {
        const int cur = it & 1;
        const bool hasNext = (it + 1 < NTT);
        if (hasNext) {
            const float* Ap2 = Ap + (it + 1) * 16;
            a0 = *(const float4*)Ap2;
            a1 = *(const float4*)(Ap2 + 4);
            const float* Bp2 = Bp + (size_t)(it + 1) * 16 * N;
#pragma unroll
            for (int i = 0; i < 8; i++) bv[i] = Bp2[(size_t)i * N];
        }

        const unsigned ab = asb + cur * 8192;
        const unsigned bbv = bsb + cur * 8192;
#pragma unroll
        for (int ks = 0; ks < 2; ks++) {
            unsigned af[2][4];
#pragma unroll
            for (int mi = 0; mi < 2; mi++)
                ldsm4(af[mi][0], af[mi][1], af[mi][2], af[mi][3],
                      ab + aoff[ks][mi]);
#pragma unroll
            for (int njp = 0; njp < 4; njp++) {
                unsigned b0, b1, b2, b3;
                ldsm4(b0, b1, b2, b3, bbv + boff[ks][njp]);
                unsigned bfa[2] = {b0, b2};
                unsigned bfb[2] = {b1, b3};
                mma8(acc[0][2 * njp], af[0], bfa);
                mma8(acc[1][2 * njp], af[1], bfa);
                mma8(acc[0][2 * njp + 1], af[0], bfb);
                mma8(acc[1][2 * njp + 1], af[1], bfb);
            }
        }

        if (hasNext) {
            const int nxt = cur ^ 1;
            *(float4*)&As[nxt][sa0] = a0;
            *(float4*)&As[nxt][sa1] = a1;
            *(float4*)&Bs[nxt][sb0] = make_float4(bv[0], bv[1], bv[2], bv[3]);
            *(float4*)&Bs[nxt][sb1] = make_float4(bv[4], bv[5], bv[6], bv[7]);
        }
        __syncthreads();
    }

    // Epilogue
#pragma unroll
    for (int mi = 0; mi < 2; mi++) {
        const int mA = bm + wm + 16 * mi + g;  // rows mA (c0,c1), mA+8 (c2,c3)
        if (MODE == 0) {
            const int bb2 = mA >> 11;
            const int ttA = mA & 2047;
#pragma unroll
            for (int nj = 0; nj < 8; nj++) {
                const int n = bn + wn + 8 * nj + 2 * r;
                const int sel = n >> 10;
                const int c = n & 1023;
                const int hh = c >> 6;
                const int dd = c & 63;
                float* dst = (sel == 0) ? g_Q : (sel == 1 ? g_K : g_V);
                float* base = dst + (((size_t)bb2 * HH + hh) * TT) * DD + dd;
                *(float2*)(base + (size_t)ttA * DD) =
                    make_float2(tf32f(acc[mi][nj][0]), tf32f(acc[mi][nj][1]));
                *(float2*)(base + (size_t)(ttA + 8) * DD) =
                    make_float2(tf32f(acc[mi][nj][2]), tf32f(acc[mi][nj][3]));
            }
        } else {
#pragma unroll
            for (int nj = 0; nj < 8; nj++) {
                const int n = bn + wn + 8 * nj + 2 * r;
                *(float2*)&C[(size_t)mA * N + n] =
                    make_float2(acc[mi][nj][0], acc[mi][nj][1]);
                *(float2*)&C[(size_t)(mA + 8) * N + n] =
                    make_float2(acc[mi][nj][2], acc[mi][nj][3]);
            }
        }
    }
}

// ---------------------------------------------------------------------------
// Flash attention, tf32 MMA, ldmatrix-fed, no in-loop cvt (Q/K/V pre-rounded).
// Block = 128 q-rows of one (b,h), 8 warps. KV tiles of 64.
// Warp owns 16 q rows. Online softmax in log2 domain.
// ---------------------------------------------------------------------------
__global__ __launch_bounds__(256) void attn_mma_kernel()
{
    const int bh = blockIdx.y;
    const int b = bh >> 4, h = bh & 15;
    const int qi = gridDim.x - 1 - blockIdx.x;  // heavy blocks first
    const int q0 = qi * 128;
    const int tid = threadIdx.x;
    const int w = tid >> 5, lane = tid & 31;
    const int g = lane >> 2, r = lane & 3;
    const int rl = (lane & 7) + ((lane >> 3) & 1) * 8;
    const int chi = lane >> 4;

    __shared__ float Ks[4096];  // [kv=64][d=64], swizzled (idx64)
    __shared__ float Vs[4096];  // [d=64][kv=64], swizzled (idx64)

    const unsigned ksb = (unsigned)__cvta_generic_to_shared(&Ks[0]);
    const unsigned vsb = (unsigned)__cvta_generic_to_shared(&Vs[0]);

    const size_t hoff = ((size_t)b * HH + h) * TT * DD;
    const float* Qg = g_Q + hoff;
    const float* Kg = g_K + hoff;
    const float* Vg = g_V + hoff;

    // Q fragments straight from gmem (read once, already tf32-exact)
    const int mrow = q0 + 16 * w + g;
    unsigned qf[8][4];
#pragma unroll
    for (int ks = 0; ks < 8; ks++) {
        qf[ks][0] = __float_as_uint(Qg[(size_t)mrow * DD + 8 * ks + r]);
        qf[ks][1] = __float_as_uint(Qg[(size_t)(mrow + 8) * DD + 8 * ks + r]);
        qf[ks][2] = __float_as_uint(Qg[(size_t)mrow * DD + 8 * ks + 4 + r]);
        qf[ks][3] = __float_as_uint(Qg[(size_t)(mrow + 8) * DD + 8 * ks + 4 + r]);
    }

    float oacc[8][4];
#pragma unroll
    for (int dt = 0; dt < 8; dt++)
#pragma unroll
        for (int c = 0; c < 4; c++) oacc[dt][c] = 0.0f;
    float mA = -1e30f, mB = -1e30f, lA = 0.0f, lB = 0.0f;

    const int qA = mrow;
    const int qB = mrow + 8;

    // Staging assignments
    const int dqK = tid & 15;   // K: d chunk
    const int kvK = tid >> 4;   // K: kv row base (0..15)
    const int dV = tid & 63;    // V: d row
    const int cgV = tid >> 6;   // V: chunk group (0..3)

    for (int kv0 = 0; kv0 < q0 + 128; kv0 += 64) {
        __syncthreads();
        // K tile: rows kv, 64 d, coalesced LDG.128 + swizzled STS.128
#pragma unroll
        for (int j = 0; j < 4; j++) {
            const int row = kvK + 16 * j;
            *(float4*)&Ks[idx64(row, dqK)] =
                *(const float4*)&Kg[(size_t)(kv0 + row) * DD + 4 * dqK];
        }
        // V tile transposed: rows d, chunks of 4 kv
#pragma unroll
        for (int i = 0; i < 4; i++) {
            const int c = 4 * cgV + i;
            const int kvb = kv0 + 4 * c;
            float4 vv;
            vv.x = Vg[(size_t)(kvb + 0) * DD + dV];
            vv.y = Vg[(size_t)(kvb + 1) * DD + dV];
            vv.z = Vg[(size_t)(kvb + 2) * DD + dV];
            vv.w = Vg[(size_t)(kvb + 3) * DD + dV];
            *(float4*)&Vs[idx64(dV, c)] = vv;
        }
        __syncthreads();

        // Warps whose rows are entirely below this KV tile skip all compute
        if (kv0 > q0 + 16 * w + 15) continue;

        // S = Q K^T  (warp: 16 x 64)
        float sacc[8][4];
#pragma unroll
        for (int j = 0; j < 8; j++)
#pragma unroll
            for (int c = 0; c < 4; c++) sacc[j][c] = 0.0f;
#pragma unroll
        for (int ks = 0; ks < 8; ks++) {
            const int c = 2 * ks + chi;
#pragma unroll
            for (int njp = 0; njp < 4; njp++) {
                const int row = 16 * njp + rl;
                unsigned b0, b1, b2, b3;
                ldsm4(b0, b1, b2, b3, ksb + 4 * idx64(row, c));
                unsigned bfa[2] = {b0, b2};
                unsigned bfb[2] = {b1, b3};
                mma8(sacc[2 * njp], qf[ks], bfa);
                mma8(sacc[2 * njp + 1], qf[ks], bfb);
            }
        }

        // scale to log2 domain + causal mask, track tile row max
        const bool diag = (kv0 + 63 > q0 + 16 * w);
        float tmA = -1e30f, tmB = -1e30f;
#pragma unroll
        for (int j = 0; j < 8; j++) {
            const int kc = kv0 + 8 * j + 2 * r;
            float t0 = sacc[j][0] * SC_LOG2E;
            float t1 = sacc[j][1] * SC_LOG2E;
            float t2 = sacc[j][2] * SC_LOG2E;
            float t3 = sacc[j][3] * SC_LOG2E;
            if (diag) {
                if (kc > qA) t0 = -1e30f;
                if (kc + 1 > qA) t1 = -1e30f;
                if (kc > qB) t2 = -1e30f;
                if (kc + 1 > qB) t3 = -1e30f;
            }
            sacc[j][0] = t0; sacc[j][1] = t1; sacc[j][2] = t2; sacc[j][3] = t3;
            tmA = fmaxf(tmA, fmaxf(t0, t1));
            tmB = fmaxf(tmB, fmaxf(t2, t3));
        }
        tmA = fmaxf(tmA, __shfl_xor_sync(FULLM, tmA, 1));
        tmA = fmaxf(tmA, __shfl_xor_sync(FULLM, tmA, 2));
        tmB = fmaxf(tmB, __shfl_xor_sync(FULLM, tmB, 1));
        tmB = fmaxf(tmB, __shfl_xor_sync(FULLM, tmB, 2));

        const float mnA = fmaxf(mA, tmA);
        const float mnB = fmaxf(mB, tmB);
        const float scA = exp2f(mA - mnA);
        const float scB = exp2f(mB - mnB);
        mA = mnA; mB = mnB;

        // exponentiate (tf32-rounded so l matches the PV numerator), row sums
        float smA = 0.0f, smB = 0.0f;
#pragma unroll
        for (int j = 0; j < 8; j++) {
            float p0 = tf32f(exp2f(sacc[j][0] - mA));
            float p1 = tf32f(exp2f(sacc[j][1] - mA));
            float p2 = tf32f(exp2f(sacc[j][2] - mB));
            float p3 = tf32f(exp2f(sacc[j][3] - mB));
            sacc[j][0] = p0; sacc[j][1] = p1; sacc[j][2] = p2; sacc[j][3] = p3;
            smA += p0 + p1;
            smB += p2 + p3;
        }
        smA += __shfl_xor_sync(FULLM, smA, 1);
        smA += __shfl_xor_sync(FULLM, smA, 2);
        smB += __shfl_xor_sync(FULLM, smB, 1);
        smB += __shfl_xor_sync(FULLM, smB, 2);
        lA = lA * scA + smA;
        lB = lB * scB + smB;

        // rescale O
#pragma unroll
        for (int dt = 0; dt < 8; dt++) {
            oacc[dt][0] *= scA; oacc[dt][1] *= scA;
            oacc[dt][2] *= scB; oacc[dt][3] *= scB;
        }

        // O += P @ V  (P: C-frag -> A-frag via shfl; V B-frags via ldsm)
        const int s0 = (lane & ~3) | (r >> 1);
        const int s1 = s0 + 2;
        const bool odd = (r & 1);
#pragma unroll
        for (int ks = 0; ks < 8; ks++) {
            float p00 = __shfl_sync(FULLM, sacc[ks][0], s0);
            float p01 = __shfl_sync(FULLM, sacc[ks][1], s0);
            float p02 = __shfl_sync(FULLM, sacc[ks][2], s0);
            float p03 = __shfl_sync(FULLM, sacc[ks][3], s0);
            float p10 = __shfl_sync(FULLM, sacc[ks][0], s1);
            float p11 = __shfl_sync(FULLM, sacc[ks][1], s1);
            float p12 = __shfl_sync(FULLM, sacc[ks][2], s1);
            float p13 = __shfl_sync(FULLM, sacc[ks][3], s1);
            unsigned pf[4];
            pf[0] = __float_as_uint(odd ? p01 : p00);
            pf[1] = __float_as_uint(odd ? p03 : p02);
            pf[2] = __float_as_uint(odd ? p11 : p10);
            pf[3] = __float_as_uint(odd ? p13 : p12);
            const int c = 2 * ks + chi;
#pragma unroll
            for (int dtp = 0; dtp < 4; dtp++) {
                const int row = 16 * dtp + rl;
                unsigned b0, b1, b2, b3;
                ldsm4(b0, b1, b2, b3, vsb + 4 * idx64(row, c));
                unsigned bfa[2] = {b0, b2};
                unsigned bfb[2] = {b1, b3};
                mma8(oacc[2 * dtp], pf, bfa);
                mma8(oacc[2 * dtp + 1], pf, bfb);
            }
        }
    }

    // Epilogue: y[b, t, h*64 + d], tf32-rounded for the proj GEMM
    const float ivA = 1.0f / lA;
    const float ivB = 1.0f / lB;
    float* yA = g_Y + ((size_t)b * TT + qA) * CC + h * DD;
    float* yB = g_Y + ((size_t)b * TT + qB) * CC + h * DD;
#pragma unroll
    for (int dt = 0; dt < 8; dt++) {
        const int d = 8 * dt + 2 * r;
        *(float2*)(yA + d) =
            make_float2(tf32f(oacc[dt][0] * ivA), tf32f(oacc[dt][1] * ivA));
        *(float2*)(yB + d) =
            make_float2(tf32f(oacc[dt][2] * ivB), tf32f(oacc[dt][3] * ivB));
    }
}

// ---------------------------------------------------------------------------
extern "C" void kernel_launch(void* const* d_in, const int* in_sizes, int n_in,
                              void* d_out, int out_size)
{
    const float* x = (const float*)d_in[0];       // [B,T,C]
    const float* W_attn = (const float*)d_in[1];  // [C,3C]
    const float* W_proj = (const float*)d_in[2];  // [C,C]
    float* out = (float*)d_out;                   // [B,T,C]

    (void)in_sizes; (void)n_in; (void)out_size;

    void *xp = nullptr, *wap = nullptr, *wpp = nullptr, *yp = nullptr;
    cudaGetSymbolAddress(&xp, g_X);
    cudaGetSymbolAddress(&wap, g_Wa);
    cudaGetSymbolAddress(&wpp, g_Wp);
    cudaGetSymbolAddress(&yp, g_Y);

    // 0) Pre-round inputs to tf32-exact fp32
    {
        const int nx4 = MTOT * CC / 4, na4 = CC * 3 * CC / 4, np4 = CC * CC / 4;
        round_tf32_kernel<<<(nx4 + 255) / 256, 256>>>(x, (float*)xp, nx4);
        round_tf32_kernel<<<(na4 + 255) / 256, 256>>>(W_attn, (float*)wap, na4);
        round_tf32_kernel<<<(np4 + 255) / 256, 256>>>(W_proj, (float*)wpp, np4);
    }
    // 1) QKV projection (tf32 MMA) with scatter into Q/K/V
    {
        dim3 grid(3 * CC / 128, MTOT / 128);  // (24, 64)
        gemm_tf32<0><<<grid, 256>>>((const float*)xp, (const float*)wap,
                                    nullptr, MTOT, 3 * CC, CC);
    }
    // 2) Causal flash attention (tf32 MMA) -> g_Y [B,T,C]
    {
        dim3 grid(TT / 128, BB * HH);  // (16, 64)
        attn_mma_kernel<<<grid, 256>>>();
    }
    // 3) Output projection (tf32 MMA)
    {
        dim3 grid(CC / 128, MTOT / 128);  // (8, 64)
        gemm_tf32<1><<<grid, 256>>>((const float*)yp, (const float*)wpp, out,
                                    MTOT, CC, CC);
    }
}

// round 6
// speedup vs baseline: 2.0739x; 1.9406x over previous
#include <cuda_runtime.h>
#include <cuda_fp16.h>
#include <math.h>

// Problem constants
#define BB 4
#define TT 2048
#define CC 1024
#define HH 16
#define DD 64
#define MTOT (BB * TT)          // 8192
#define FULLM 0xffffffffu
#define SC_LOG2E 0.18033688f    // (1/sqrt(64)) * log2(e)

// Scratch (allocation is banned -> __device__ globals)
__device__ __half g_Qh[BB * HH * TT * DD];
__device__ __half g_Kh[BB * HH * TT * DD];
__device__ __half g_Vh[BB * HH * TT * DD];
__device__ __half g_Yh[MTOT * CC];
__device__ __half g_Xh[MTOT * CC];          // fp16 x            [M][C]
__device__ __half g_Wah[3 * CC * CC];       // fp16 W_attn^T     [3C][C]
__device__ __half g_Wph[CC * CC];           // fp16 W_proj^T     [C][C]

// ---------------------------------------------------------------------------
// MMA + LDSM helpers (fp16, fp32 accum)
// ---------------------------------------------------------------------------
__device__ __forceinline__ void mma16(float* c, const unsigned* a, const unsigned* b) {
    asm volatile(
        "mma.sync.aligned.m16n8k16.row.col.f32.f16.f16.f32 "
        "{%0,%1,%2,%3}, {%4,%5,%6,%7}, {%8,%9}, {%0,%1,%2,%3};\n"
        : "+f"(c[0]), "+f"(c[1]), "+f"(c[2]), "+f"(c[3])
        : "r"(a[0]), "r"(a[1]), "r"(a[2]), "r"(a[3]), "r"(b[0]), "r"(b[1]));
}
__device__ __forceinline__ void ldsm4(unsigned& r0, unsigned& r1, unsigned& r2,
                                      unsigned& r3, unsigned addr) {
    asm volatile("ldmatrix.sync.aligned.m8n8.x4.shared.b16 {%0,%1,%2,%3}, [%4];"
                 : "=r"(r0), "=r"(r1), "=r"(r2), "=r"(r3) : "r"(addr));
}
__device__ __forceinline__ void ldsm4t(unsigned& r0, unsigned& r1, unsigned& r2,
                                       unsigned& r3, unsigned addr) {
    asm volatile("ldmatrix.sync.aligned.m8n8.x4.trans.shared.b16 {%0,%1,%2,%3}, [%4];"
                 : "=r"(r0), "=r"(r1), "=r"(r2), "=r"(r3) : "r"(addr));
}

// Swizzled smem layouts (half-element indices; chunks of 8 halfs = 16B)
// 64B rows (GEMM tiles, 32 halfs/row): c in 0..3
__device__ __forceinline__ int hswz64(int row, int c) {
    return ((row >> 1) << 6) + ((((c) + ((row & 1) << 2)) ^ ((row >> 1) & 7)) << 3);
}
// 128B rows (attention tiles, 64 halfs/row): c in 0..7
__device__ __forceinline__ int hswz128(int row, int c) {
    return (row << 6) + (((c) ^ (row & 7)) << 3);
}

// ---------------------------------------------------------------------------
// Pre-pass kernels
// ---------------------------------------------------------------------------
__global__ void f2h_kernel(const float* __restrict__ in,
                           __half* __restrict__ out, int n4)
{
    const int i = blockIdx.x * blockDim.x + threadIdx.x;
    if (i < n4) {
        float4 v = ((const float4*)in)[i];
        __half2 h0 = __floats2half2_rn(v.x, v.y);
        __half2 h1 = __floats2half2_rn(v.z, v.w);
        ((__half2*)out)[2 * i] = h0;
        ((__half2*)out)[2 * i + 1] = h1;
    }
}

// in [K][N] fp32 -> out [N][K] fp16
__global__ void transpose_f2h_kernel(const float* __restrict__ in,
                                     __half* __restrict__ out, int K, int N)
{
    __shared__ float t[32][33];
    const int n0 = blockIdx.x * 32, k0 = blockIdx.y * 32;
    const int tx = threadIdx.x, ty = threadIdx.y;  // 32 x 8
#pragma unroll
    for (int i = 0; i < 32; i += 8)
        t[ty + i][tx] = in[(size_t)(k0 + ty + i) * N + n0 + tx];
    __syncthreads();
#pragma unroll
    for (int i = 0; i < 32; i += 8)
        out[(size_t)(n0 + ty + i) * K + k0 + tx] = __float2half_rn(t[tx][ty + i]);
}

// ---------------------------------------------------------------------------
// FP16 tensor-core GEMM: C[M,N] = A[M,K] @ B[N,K]^T   (B pre-transposed)
// 128x128 block, BK=32, 256 threads (8 warps 4x2; warp tile 32x64).
// MODE 0: scatter into g_Qh/g_Kh/g_Vh ([B,H,T,D] fp16); MODE 1: fp32 store.
// ---------------------------------------------------------------------------
template <int MODE>
__global__ __launch_bounds__(256, 2) void gemm_h(
    const __half* __restrict__ A, const __half* __restrict__ Bm,
    float* __restrict__ C, int M, int N, int K)
{
    __shared__ __half As[2][4096];
    __shared__ __half Bs[2][4096];

    const int tid = threadIdx.x;
    const int bm = blockIdx.y * 128;
    const int bn = blockIdx.x * 128;
    const int lane = tid & 31, wid = tid >> 5;
    const int wm = (wid & 3) * 32;
    const int wn = (wid >> 2) * 64;
    const int g = lane >> 2, r = lane & 3;
    const int rl = (lane & 7) + ((lane >> 3) & 1) * 8;  // ldsm row offset
    const int chi = lane >> 4;                          // ldsm chunk offset

    // Loaders: one row (64B) per 2 threads, 2 chunks each
    const int lr = tid >> 1;            // row 0..127
    const int cb = (tid & 1) * 2;       // chunk base

    const __half* Ap = A + (size_t)(bm + lr) * K + cb * 8;
    const __half* Bp = Bm + (size_t)(bn + lr) * K + cb * 8;

    // Hoisted ldsm byte offsets (k-loop invariant)
    unsigned aoff[2][2], boff[2][4];
#pragma unroll
    for (int ks = 0; ks < 2; ks++) {
        const int c = 2 * ks + chi;
#pragma unroll
        for (int mi = 0; mi < 2; mi++)
            aoff[ks][mi] = 2 * hswz64(wm + 16 * mi + rl, c);
#pragma unroll
        for (int njp = 0; njp < 4; njp++)
            boff[ks][njp] = 2 * hswz64(wn + 16 * njp + rl, c);
    }

    const int sa0 = hswz64(lr, cb), sa1 = hswz64(lr, cb + 1);

    uint4 av0 = *(const uint4*)Ap;
    uint4 av1 = *(const uint4*)(Ap + 8);
    uint4 bv0 = *(const uint4*)Bp;
    uint4 bv1 = *(const uint4*)(Bp + 8);

    // Stage 0
    *(uint4*)&As[0][sa0] = av0;
    *(uint4*)&As[0][sa1] = av1;
    *(uint4*)&Bs[0][sa0] = bv0;
    *(uint4*)&Bs[0][sa1] = bv1;
    __syncthreads();

    float acc[2][8][4];
#pragma unroll
    for (int mi = 0; mi < 2; mi++)
#pragma unroll
        for (int nj = 0; nj < 8; nj++)
#pragma unroll
            for (int c = 0; c < 4; c++) acc[mi][nj][c] = 0.0f;

    const unsigned asb = (unsigned)__cvta_generic_to_shared(&As[0][0]);
    const unsigned bsb = (unsigned)__cvta_generic_to_shared(&Bs[0][0]);

    const int NTT = K / 32;
    for (int it = 0; it < NTT; it++) {
        const int cur = it & 1;
        const bool hasNext = (it + 1 < NTT);
        if (hasNext) {
            const __half* Ap2 = Ap + (it + 1) * 32;
            const __half* Bp2 = Bp + (it + 1) * 32;
            av0 = *(const uint4*)Ap2;
            av1 = *(const uint4*)(Ap2 + 8);
            bv0 = *(const uint4*)Bp2;
            bv1 = *(const uint4*)(Bp2 + 8);
        }

        const unsigned ab = asb + cur * 8192;
        const unsigned bbv = bsb + cur * 8192;
#pragma unroll
        for (int ks = 0; ks < 2; ks++) {
            unsigned af[2][4];
#pragma unroll
            for (int mi = 0; mi < 2; mi++)
                ldsm4(af[mi][0], af[mi][1], af[mi][2], af[mi][3],
                      ab + aoff[ks][mi]);
#pragma unroll
            for (int njp = 0; njp < 4; njp++) {
                unsigned b0, b1, b2, b3;
                ldsm4(b0, b1, b2, b3, bbv + boff[ks][njp]);
                unsigned bfa[2] = {b0, b2};
                unsigned bfb[2] = {b1, b3};
                mma16(acc[0][2 * njp], af[0], bfa);
                mma16(acc[1][2 * njp], af[1], bfa);
                mma16(acc[0][2 * njp + 1], af[0], bfb);
                mma16(acc[1][2 * njp + 1], af[1], bfb);
            }
        }

        if (hasNext) {
            const int nxt = cur ^ 1;
            *(uint4*)&As[nxt][sa0] = av0;
            *(uint4*)&As[nxt][sa1] = av1;
            *(uint4*)&Bs[nxt][sa0] = bv0;
            *(uint4*)&Bs[nxt][sa1] = bv1;
        }
        __syncthreads();
    }

    // Epilogue
#pragma unroll
    for (int mi = 0; mi < 2; mi++) {
        const int mA = bm + wm + 16 * mi + g;  // rows mA (c0,c1), mA+8 (c2,c3)
        if (MODE == 0) {
            const int bb2 = mA >> 11;
            const int ttA = mA & 2047;
#pragma unroll
            for (int nj = 0; nj < 8; nj++) {
                const int n = bn + wn + 8 * nj + 2 * r;
                const int sel = n >> 10;
                const int c = n & 1023;
                const int hh = c >> 6;
                const int dd = c & 63;
                __half* dst = (sel == 0) ? g_Qh : (sel == 1 ? g_Kh : g_Vh);
                __half* base = dst + (((size_t)bb2 * HH + hh) * TT) * DD + dd;
                *(__half2*)(base + (size_t)ttA * DD) =
                    __floats2half2_rn(acc[mi][nj][0], acc[mi][nj][1]);
                *(__half2*)(base + (size_t)(ttA + 8) * DD) =
                    __floats2half2_rn(acc[mi][nj][2], acc[mi][nj][3]);
            }
        } else {
#pragma unroll
            for (int nj = 0; nj < 8; nj++) {
                const int n = bn + wn + 8 * nj + 2 * r;
                *(float2*)&C[(size_t)mA * N + n] =
                    make_float2(acc[mi][nj][0], acc[mi][nj][1]);
                *(float2*)&C[(size_t)(mA + 8) * N + n] =
                    make_float2(acc[mi][nj][2], acc[mi][nj][3]);
            }
        }
    }
}

// ---------------------------------------------------------------------------
// Flash attention, fp16 MMA. Block = 128 q-rows of one (b,h), 8 warps.
// KV tiles of 64. Warp owns 16 q rows. K and V stored natural [kv][d];
// V B-fragments via ldmatrix.trans. P stays in-lane (no shuffles).
// ---------------------------------------------------------------------------
__global__ __launch_bounds__(256) void attn_mma_kernel()
{
    const int bh = blockIdx.y;
    const int b = bh >> 4, h = bh & 15;
    const int qi = gridDim.x - 1 - blockIdx.x;  // heavy blocks first
    const int q0 = qi * 128;
    const int tid = threadIdx.x;
    const int w = tid >> 5, lane = tid & 31;
    const int g = lane >> 2, r = lane & 3;
    const int rl = (lane & 7) + ((lane >> 3) & 1) * 8;
    const int chi = lane >> 4;

    __shared__ __half Ks[4096];  // [kv=64][d=64], SW128
    __shared__ __half Vs[4096];  // [kv=64][d=64], SW128

    const unsigned ksb = (unsigned)__cvta_generic_to_shared(&Ks[0]);
    const unsigned vsb = (unsigned)__cvta_generic_to_shared(&Vs[0]);

    const size_t hoff = ((size_t)b * HH + h) * TT * DD;
    const __half* Qg = g_Qh + hoff;
    const __half* Kg = g_Kh + hoff;
    const __half* Vg = g_Vh + hoff;

    // Q fragments straight from gmem (read once)
    const int mrow = q0 + 16 * w + g;
    const __half* Qr0 = Qg + (size_t)mrow * DD;
    const __half* Qr1 = Qg + (size_t)(mrow + 8) * DD;
    unsigned qf[4][4];
#pragma unroll
    for (int ks = 0; ks < 4; ks++) {
        qf[ks][0] = *(const unsigned*)(Qr0 + 16 * ks + 2 * r);
        qf[ks][1] = *(const unsigned*)(Qr1 + 16 * ks + 2 * r);
        qf[ks][2] = *(const unsigned*)(Qr0 + 16 * ks + 8 + 2 * r);
        qf[ks][3] = *(const unsigned*)(Qr1 + 16 * ks + 8 + 2 * r);
    }

    // Hoisted ldsm byte offsets
    unsigned koff[4][4], voff[4][4];
#pragma unroll
    for (int ks = 0; ks < 4; ks++)
#pragma unroll
        for (int p = 0; p < 4; p++) {
            koff[ks][p] = 2 * hswz128(16 * p + rl, 2 * ks + chi);   // S: B=K
            voff[ks][p] = 2 * hswz128(16 * ks + rl, 2 * p + chi);   // PV: B=V^T
        }

    float oacc[8][4];
#pragma unroll
    for (int dt = 0; dt < 8; dt++)
#pragma unroll
        for (int c = 0; c < 4; c++) oacc[dt][c] = 0.0f;
    float mA = -1e30f, mB = -1e30f, lA = 0.0f, lB = 0.0f;

    const int qA = mrow;
    const int qB = mrow + 8;

    // Staging: row = tid>>2 (0..63), 2 chunks per thread
    const int srow = tid >> 2;
    const int scb = (tid & 3) * 2;
    const int ss0 = hswz128(srow, scb), ss1 = hswz128(srow, scb + 1);

    for (int kv0 = 0; kv0 < q0 + 128; kv0 += 64) {
        __syncthreads();
        {
            const __half* Kp = Kg + (size_t)(kv0 + srow) * DD + scb * 8;
            const __half* Vp = Vg + (size_t)(kv0 + srow) * DD + scb * 8;
            *(uint4*)&Ks[ss0] = *(const uint4*)Kp;
            *(uint4*)&Ks[ss1] = *(const uint4*)(Kp + 8);
            *(uint4*)&Vs[ss0] = *(const uint4*)Vp;
            *(uint4*)&Vs[ss1] = *(const uint4*)(Vp + 8);
        }
        __syncthreads();

        // Warps whose rows are entirely below this KV tile skip all compute
        if (kv0 > q0 + 16 * w + 15) continue;

        // S = Q K^T  (warp: 16 x 64)
        float sacc[8][4];
#pragma unroll
        for (int j = 0; j < 8; j++)
#pragma unroll
            for (int c = 0; c < 4; c++) sacc[j][c] = 0.0f;
#pragma unroll
        for (int ks = 0; ks < 4; ks++) {
#pragma unroll
            for (int njp = 0; njp < 4; njp++) {
                unsigned b0, b1, b2, b3;
                ldsm4(b0, b1, b2, b3, ksb + koff[ks][njp]);
                unsigned bfa[2] = {b0, b2};
                unsigned bfb[2] = {b1, b3};
                mma16(sacc[2 * njp], qf[ks], bfa);
                mma16(sacc[2 * njp + 1], qf[ks], bfb);
            }
        }

        // scale to log2 domain + causal mask, track tile row max
        const bool diag = (kv0 + 63 > q0 + 16 * w);
        float tmA = -1e30f, tmB = -1e30f;
#pragma unroll
        for (int j = 0; j < 8; j++) {
            const int kc = kv0 + 8 * j + 2 * r;
            float t0 = sacc[j][0] * SC_LOG2E;
            float t1 = sacc[j][1] * SC_LOG2E;
            float t2 = sacc[j][2] * SC_LOG2E;
            float t3 = sacc[j][3] * SC_LOG2E;
            if (diag) {
                if (kc > qA) t0 = -1e30f;
                if (kc + 1 > qA) t1 = -1e30f;
                if (kc > qB) t2 = -1e30f;
                if (kc + 1 > qB) t3 = -1e30f;
            }
            sacc[j][0] = t0; sacc[j][1] = t1; sacc[j][2] = t2; sacc[j][3] = t3;
            tmA = fmaxf(tmA, fmaxf(t0, t1));
            tmB = fmaxf(tmB, fmaxf(t2, t3));
        }
        tmA = fmaxf(tmA, __shfl_xor_sync(FULLM, tmA, 1));
        tmA = fmaxf(tmA, __shfl_xor_sync(FULLM, tmA, 2));
        tmB = fmaxf(tmB, __shfl_xor_sync(FULLM, tmB, 1));
        tmB = fmaxf(tmB, __shfl_xor_sync(FULLM, tmB, 2));

        const float mnA = fmaxf(mA, tmA);
        const float mnB = fmaxf(mB, tmB);
        const float scA = exp2f(mA - mnA);
        const float scB = exp2f(mB - mnB);
        mA = mnA; mB = mnB;

        // exponentiate; fp16-round P (so l matches PV numerator); pack A-frags
        unsigned pA[8], pB[8];
        float smA = 0.0f, smB = 0.0f;
#pragma unroll
        for (int j = 0; j < 8; j++) {
            __half h0 = __float2half_rn(exp2f(sacc[j][0] - mA));
            __half h1 = __float2half_rn(exp2f(sacc[j][1] - mA));
            __half h2 = __float2half_rn(exp2f(sacc[j][2] - mB));
            __half h3 = __float2half_rn(exp2f(sacc[j][3] - mB));
            pA[j] = (unsigned)__half_as_ushort(h0) |
                    ((unsigned)__half_as_ushort(h1) << 16);
            pB[j] = (unsigned)__half_as_ushort(h2) |
                    ((unsigned)__half_as_ushort(h3) << 16);
            smA += __half2float(h0) + __half2float(h1);
            smB += __half2float(h2) + __half2float(h3);
        }
        smA += __shfl_xor_sync(FULLM, smA, 1);
        smA += __shfl_xor_sync(FULLM, smA, 2);
        smB += __shfl_xor_sync(FULLM, smB, 1);
        smB += __shfl_xor_sync(FULLM, smB, 2);
        lA = lA * scA + smA;
        lB = lB * scB + smB;

        // rescale O
#pragma unroll
        for (int dt = 0; dt < 8; dt++) {
            oacc[dt][0] *= scA; oacc[dt][1] *= scA;
            oacc[dt][2] *= scB; oacc[dt][3] *= scB;
        }

        // O += P @ V  (P A-frags in-lane; V B-frags via ldmatrix.trans)
#pragma unroll
        for (int ks = 0; ks < 4; ks++) {
            unsigned pf[4] = {pA[2 * ks], pB[2 * ks],
                              pA[2 * ks + 1], pB[2 * ks + 1]};
#pragma unroll
            for (int dtp = 0; dtp < 4; dtp++) {
                unsigned b0, b1, b2, b3;
                ldsm4t(b0, b1, b2, b3, vsb + voff[ks][dtp]);
                unsigned bfa[2] = {b0, b1};
                unsigned bfb[2] = {b2, b3};
                mma16(oacc[2 * dtp], pf, bfa);
                mma16(oacc[2 * dtp + 1], pf, bfb);
            }
        }
    }

    // Epilogue: y fp16 [b, t, h*64 + d]
    const float ivA = 1.0f / lA;
    const float ivB = 1.0f / lB;
    __half* yA = g_Yh + ((size_t)b * TT + qA) * CC + h * DD;
    __half* yB = g_Yh + ((size_t)b * TT + qB) * CC + h * DD;
#pragma unroll
    for (int dt = 0; dt < 8; dt++) {
        const int d = 8 * dt + 2 * r;
        *(__half2*)(yA + d) =
            __floats2half2_rn(oacc[dt][0] * ivA, oacc[dt][1] * ivA);
        *(__half2*)(yB + d) =
            __floats2half2_rn(oacc[dt][2] * ivB, oacc[dt][3] * ivB);
    }
}

// ---------------------------------------------------------------------------
extern "C" void kernel_launch(void* const* d_in, const int* in_sizes, int n_in,
                              void* d_out, int out_size)
{
    const float* x = (const float*)d_in[0];       // [B,T,C]
    const float* W_attn = (const float*)d_in[1];  // [C,3C]
    const float* W_proj = (const float*)d_in[2];  // [C,C]
    float* out = (float*)d_out;                   // [B,T,C]

    (void)in_sizes; (void)n_in; (void)out_size;

    void *xp = nullptr, *wap = nullptr, *wpp = nullptr, *yp = nullptr;
    cudaGetSymbolAddress(&xp, g_Xh);
    cudaGetSymbolAddress(&wap, g_Wah);
    cudaGetSymbolAddress(&wpp, g_Wph);
    cudaGetSymbolAddress(&yp, g_Yh);

    // 0) Pre-pass: x -> fp16; weights -> fp16 transposed [N][K]
    {
        const int nx4 = MTOT * CC / 4;
        f2h_kernel<<<(nx4 + 255) / 256, 256>>>(x, (__half*)xp, nx4);
        dim3 blk(32, 8);
        transpose_f2h_kernel<<<dim3(3 * CC / 32, CC / 32), blk>>>(
            W_attn, (__half*)wap, CC, 3 * CC);
        transpose_f2h_kernel<<<dim3(CC / 32, CC / 32), blk>>>(
            W_proj, (__half*)wpp, CC, CC);
    }
    // 1) QKV projection (fp16 MMA) with scatter into Q/K/V
    {
        dim3 grid(3 * CC / 128, MTOT / 128);  // (24, 64)
        gemm_h<0><<<grid, 256>>>((const __half*)xp, (const __half*)wap,
                                 nullptr, MTOT, 3 * CC, CC);
    }
    // 2) Causal flash attention (fp16 MMA) -> g_Yh [B,T,C]
    {
        dim3 grid(TT / 128, BB * HH);  // (16, 64)
        attn_mma_kernel<<<grid, 256>>>();
    }
    // 3) Output projection (fp16 MMA) -> fp32 out
    {
        dim3 grid(CC / 128, MTOT / 128);  // (8, 64)
        gemm_h<1><<<grid, 256>>>((const __half*)yp, (const __half*)wpp, out,
                                 MTOT, CC, CC);
    }
}